// round 12
// baseline (speedup 1.0000x reference)
#include <cuda_runtime.h>

#define NB 4
#define NG 8
#define HH 32
#define WW 32
#define KS 7
#define PD 3
#define HP 38
#define NPP 1444      // HP*HP
#define NM 392
#define VPAD 416      // padded S cols (stored zeros; collapse reads only m<392)
#define MSK 424       // mod32=8: K-staging STS conflict-free; mult of 4
#define QSTR 36       // q tile row stride: r0-chunks land on disjoint bank quads
#define NPIX 1024

#define SM_KS  0
#define SM_AGT (32*MSK)            // 13568 ; Agt[ij*64 + g*8 + g'] (3136)
#define SM_QS  (SM_AGT + 3136)     // 16704 ; [32 c][QSTR]
#define SM_MB  (SM_QS + 32*QSTR)   // 17856  [8w][32r]
#define SM_RI  (SM_MB + 256)       // 18112
#define ATTN_SMEM ((SM_RI + 32)*4) // 72576 B -> 3 CTA/SM

// conv kernel smem (qconv view)
#define QC_WS 0                    // [128 o][33]
#define QC_XS (128*33)             // [32 k][64 p]
#define QC_OS (QC_XS + 32*64)      // [64 p][132]
#define CONV_SMEM ((QC_OS + 64*132)*4)   // 58880 B
// kv view
#define KV_WS 0                    // [64 o][33]
#define KV_XS (64*33)              // [32 k][128 p]
#define KV_BS (KV_XS + 32*128)     // [64]

__device__ float g_q[NB*NPIX*1024];   // [b][p][g*128 + hh*32 + c]  (q * log2e)
__device__ float g_k[NB*NPP*256];     // [b][sp][c*8+g]
__device__ float g_v[NB*NPP*256];

typedef unsigned long long u64;
__device__ __forceinline__ u64 pk2(float a, float b) {
    u64 r; asm("mov.b64 %0, {%1,%2};" : "=l"(r) : "f"(a), "f"(b)); return r;
}
__device__ __forceinline__ void up2(u64 v, float& a, float& b) {
    asm("mov.b64 {%0,%1}, %2;" : "=f"(a), "=f"(b) : "l"(v));
}
#define FMA2(d,a,b) asm("fma.rn.f32x2 %0, %1, %2, %0;" : "+l"(d) : "l"(a), "l"(b))
__device__ __forceinline__ float ex2(float x) {
    float r; asm("ex2.approx.f32 %0, %1;" : "=f"(r) : "f"(x)); return r;
}

// ================= fused conv kernel =================
__global__ void __launch_bounds__(256) conv_kernel(const float* __restrict__ x,
                                                   const float* __restrict__ wq,
                                                   const float* __restrict__ bq,
                                                   const float* __restrict__ wk,
                                                   const float* __restrict__ bk,
                                                   const float* __restrict__ wv,
                                                   const float* __restrict__ bv) {
    extern __shared__ float sm[];
    int g = blockIdx.y, b = blockIdx.z;
    int t = threadIdx.x;

    if (blockIdx.x < 16) {
        // ---- qconv: per (b,g) GEMM 128o x 64p, K=32; q scaled by log2e ----
        float* Ws = sm + QC_WS;
        float* Xs = sm + QC_XS;
        float* Os = sm + QC_OS;
        int pt = blockIdx.x;
        #pragma unroll
        for (int u = 0; u < 16; u++) {
            int e = t + 256*u;
            Ws[(e >> 5)*33 + (e & 31)] = wq[g*4096 + e];
        }
        #pragma unroll
        for (int u = 0; u < 8; u++) {
            int e = t + 256*u;
            int k = e >> 6, p = e & 63;
            Xs[e] = x[((b*NG + g)*32 + k)*1024 + pt*64 + p];
        }
        __syncthreads();

        int to = t >> 4, tp = t & 15;
        int o0 = to*8, p0 = tp*4;
        u64 a[8][2];
        #pragma unroll
        for (int i = 0; i < 8; i++) {
            float bi = bq[g*128 + o0 + i];
            a[i][0] = pk2(bi, bi); a[i][1] = a[i][0];
        }
        #pragma unroll 4
        for (int k = 0; k < 32; k++) {
            ulonglong2 xv = *(const ulonglong2*)(Xs + k*64 + p0);
            #pragma unroll
            for (int i = 0; i < 8; i++) {
                float w = Ws[(o0 + i)*33 + k];
                u64 w2 = pk2(w, w);
                FMA2(a[i][0], w2, xv.x);
                FMA2(a[i][1], w2, xv.y);
            }
        }
        const float L2E = 1.4426950408889634f;
        #pragma unroll
        for (int i = 0; i < 8; i++)
            #pragma unroll
            for (int j = 0; j < 2; j++) {
                float lo, hi; up2(a[i][j], lo, hi);
                Os[(p0 + 2*j    )*132 + o0 + i] = lo * L2E;
                Os[(p0 + 2*j + 1)*132 + o0 + i] = hi * L2E;
            }
        __syncthreads();
        #pragma unroll
        for (int u = 0; u < 8; u++) {
            int e = t + 256*u;
            int p = e >> 5, o4 = e & 31;
            float4 v = *(const float4*)(Os + p*132 + o4*4);
            *(float4*)(g_q + (long)(b*1024 + pt*64 + p)*1024 + g*128 + o4*4) = v;
        }
    } else {
        // ---- kv conv: per (b,g) GEMM 64o x 128p on padded grid ----
        float* Ws = sm + KV_WS;
        float* Xs = sm + KV_XS;
        float* bs = sm + KV_BS;
        int pt = blockIdx.x - 16;
        #pragma unroll
        for (int u = 0; u < 8; u++) {
            int e = t + 256*u;
            int o = e >> 5, k = e & 31;
            Ws[o*33 + k] = (o < 32) ? wk[g*1024 + o*32 + k] : wv[g*1024 + (o-32)*32 + k];
        }
        if (t < 64) bs[t] = (t < 32) ? bk[g*32 + t] : bv[g*32 + t - 32];
        #pragma unroll
        for (int u = 0; u < 16; u++) {
            int e = t + 256*u;
            int k = e >> 7, p = e & 127;
            int sp = pt*128 + p;
            float v = 0.f;
            if (sp < NPP) {
                int sy = sp / HP, sx = sp - sy*HP;
                int iy = sy - PD, ix = sx - PD;
                if (iy >= 0 && iy < HH && ix >= 0 && ix < WW)
                    v = x[((b*NG + g)*32 + k)*1024 + iy*32 + ix];
            }
            Xs[k*128 + p] = v;
        }
        __syncthreads();

        int to = t >> 4, tp = t & 15;
        int o0 = to*4, p0 = tp*8;
        u64 acc[4][4];
        #pragma unroll
        for (int oi = 0; oi < 4; oi++) {
            float bi = bs[o0 + oi];
            u64 b2 = pk2(bi, bi);
            #pragma unroll
            for (int pp = 0; pp < 4; pp++) acc[oi][pp] = b2;
        }
        #pragma unroll 4
        for (int k = 0; k < 32; k++) {
            ulonglong2 xa = *(const ulonglong2*)(Xs + k*128 + p0);
            ulonglong2 xb = *(const ulonglong2*)(Xs + k*128 + p0 + 4);
            u64 xx[4] = {xa.x, xa.y, xb.x, xb.y};
            float wv4[4] = {Ws[(o0+0)*33 + k], Ws[(o0+1)*33 + k],
                            Ws[(o0+2)*33 + k], Ws[(o0+3)*33 + k]};
            #pragma unroll
            for (int oi = 0; oi < 4; oi++) {
                u64 w2 = pk2(wv4[oi], wv4[oi]);
                #pragma unroll
                for (int pp = 0; pp < 4; pp++) FMA2(acc[oi][pp], w2, xx[pp]);
            }
        }
        #pragma unroll
        for (int pp = 0; pp < 4; pp++)
            #pragma unroll
            for (int hf = 0; hf < 2; hf++) {
                int sp = pt*128 + p0 + pp*2 + hf;
                if (sp < NPP) {
                    long base = (long)(b*NPP + sp)*256 + g;
                    #pragma unroll
                    for (int oi = 0; oi < 4; oi++) {
                        int o = o0 + oi;
                        float lo, hi; up2(acc[oi][pp], lo, hi);
                        float val = hf ? hi : lo;
                        if (o < 32) g_k[base + o*8] = val;
                        else        g_v[base + (o-32)*8] = val;
                    }
                }
            }
    }
}

// ================= attention =================
// One S-GEMM pass: 8 rows x 4 cols per lane; acc = 16 u64 (fits 3 CTA/SM regs)
__device__ __forceinline__ void sgemm_pass(float* Ks, const float* qs,
                                           int r0, int cb, bool valid, bool active,
                                           float* rsum) {
    int lc = active ? cb : 0;
    u64 acc[8][2];
    #pragma unroll
    for (int i = 0; i < 8; i++) { acc[i][0] = 0ull; acc[i][1] = 0ull; }
    #pragma unroll 4
    for (int cc = 0; cc < 32; cc++) {
        ulonglong2 k = *(const ulonglong2*)(Ks + cc*MSK + lc);
        float4 qa = *(const float4*)(qs + cc*QSTR + r0);
        float4 qb = *(const float4*)(qs + cc*QSTR + r0 + 4);
        float qv[8] = {qa.x, qa.y, qa.z, qa.w, qb.x, qb.y, qb.z, qb.w};
        #pragma unroll
        for (int i = 0; i < 8; i++) {
            u64 q2 = pk2(qv[i], qv[i]);
            FMA2(acc[i][0], q2, k.x);
            FMA2(acc[i][1], q2, k.y);
        }
    }
    #pragma unroll
    for (int i = 0; i < 8; i++) {
        float l0, h0, l1, h1;
        up2(acc[i][0], l0, h0); up2(acc[i][1], l1, h1);
        float e0 = ex2(l0), e1 = ex2(h0), e2 = ex2(l1), e3 = ex2(h1);
        if (valid) rsum[i] += e0 + e1 + e2 + e3;
        if (active) {
            u64 s0 = valid ? pk2(e0, e1) : 0ull;
            u64 s1 = valid ? pk2(e2, e3) : 0ull;
            *(ulonglong2*)(Ks + (r0 + i)*MSK + cb) = make_ulonglong2(s0, s1);
        }
    }
}

__device__ __forceinline__ void sgemm_warp(float* Ks, const float* qs, float* mb,
                                           int w, int tx) {
    int r0 = (tx >> 3) * 8;
    int c0 = w*64 + (tx & 7)*4;      // pass 0 cols
    int c1 = c0 + 32;                // pass 1 cols
    float rsum[8];
    #pragma unroll
    for (int i = 0; i < 8; i++) rsum[i] = 0.f;
    sgemm_pass(Ks, qs, r0, c0, c0 < NM, c0 < VPAD, rsum);
    sgemm_pass(Ks, qs, r0, c1, c1 < NM, c1 < VPAD, rsum);
    #pragma unroll
    for (int i = 0; i < 8; i++) {
        float s = rsum[i];
        s += __shfl_xor_sync(0xffffffffu, s, 1);
        s += __shfl_xor_sync(0xffffffffu, s, 2);
        s += __shfl_xor_sync(0xffffffffu, s, 4);
        if ((tx & 7) == 0) mb[w*32 + r0 + i] = s;
    }
}

__global__ void __launch_bounds__(256, 3) attn_kernel(const float* __restrict__ rel_h,
                                                      const float* __restrict__ rel_w,
                                                      const float* __restrict__ gv,
                                                      float* __restrict__ out) {
    extern __shared__ float sm[];
    float* Ks   = sm + SM_KS;    // [32 c][MSK] -> E in place
    float* Agt  = sm + SM_AGT;   // [ij][g][g'] 49x8x8
    float* qs   = sm + SM_QS;    // [c][QSTR]
    float* mb   = sm + SM_MB;    // [8 w][32 r]
    float* rinv = sm + SM_RI;
    float* Rs   = Ks;            // O-GEMM partials reuse Ks (E dead by then)

    int bp = blockIdx.x;
    int b = bp >> 10, p = bp & 1023;
    int px = p >> 5, py = p & 31;
    int t = threadIdx.x;
    int tx = t & 31, ty = t >> 5;

    // stage q: qs[c*QSTR + hh*8 + g]
    {
        float4 qv = ((const float4*)(g_q + (long)bp*1024))[t];
        int s = t*4;
        int g = s >> 7, hh = (s >> 5) & 3, c0 = s & 31;
        qs[(c0+0)*QSTR + hh*8 + g] = qv.x;
        qs[(c0+1)*QSTR + hh*8 + g] = qv.y;
        qs[(c0+2)*QSTR + hh*8 + g] = qv.z;
        qs[(c0+3)*QSTR + hh*8 + g] = qv.w;
    }

    // stage K(+rel) [c][m]; STS conflict-free (MSK%32==8)
    {
        int c = t >> 3, gq = t & 7;
        float rh[KS];
        #pragma unroll
        for (int u = 0; u < KS; u++)
            rh[u] = (c < 16) ? rel_h[c*56 + gq*7 + u] : rel_w[(c - 16)*56 + gq*7 + u];
        const float* kbase = g_k + ((long)(b*HP + px)*HP + py)*256 + t;
        for (int i = 0; i < KS; i++) {
            #pragma unroll
            for (int j = 0; j < KS; j++) {
                int m = gq*49 + i*7 + j;
                int off = (i*HP + j)*256;
                float rel = (c < 16) ? rh[i] : rh[j];
                Ks[c*MSK + m] = kbase[off] + rel;
            }
        }
    }
    __syncthreads();

    // S = q^T K with fused exp + row sums (2 passes, low-reg)
    if (ty < 7) sgemm_warp(Ks, qs, mb, ty, tx);
    __syncthreads();

    if (t < 32) {
        float s = 0.f;
        #pragma unroll
        for (int w = 0; w < 7; w++) s += mb[w*32 + t];
        rinv[t] = 1.f / s;
    }
    __syncthreads();

    // collapse heads into transposed layout: Agt[ij*64 + g*8 + g'] =
    //   sum_h E[h*8+g][g'*49+ij] * rinv[h*8+g]
    for (int idx = t; idx < 3136; idx += 256) {
        int ij = idx >> 6;
        int rem = idx & 63;
        int g = rem >> 3, gp = rem & 7;
        int m = gp*49 + ij;
        float s = Ks[g*MSK + m]        * rinv[g]
                + Ks[(8+g)*MSK + m]    * rinv[8+g]
                + Ks[(16+g)*MSK + m]   * rinv[16+g]
                + Ks[(24+g)*MSK + m]   * rinv[24+g];
        Agt[idx] = s;
    }
    __syncthreads();

    // O-GEMM: V straight from gmem (coalesced, consumed once).
    {
        u64 og[8];
        #pragma unroll
        for (int g = 0; g < 8; g++) og[g] = 0ull;
        int c = tx, w = ty;
        const float* vb = gv + ((long)(b*HP + px)*HP + py)*256 + c*8;
        #pragma unroll
        for (int k = 0; k < 7; k++) {
            int ij = k*8 + w;
            if (ij < 49) {
                int i = ij / 7, j = ij - i*7;
                const float4* vp = (const float4*)(vb + (i*HP + j)*256);
                float4 va = vp[0], vbq = vp[1];
                u64 v0 = pk2(va.x, va.y), v1 = pk2(va.z, va.w);
                u64 v2 = pk2(vbq.x, vbq.y), v3 = pk2(vbq.z, vbq.w);
                const float* ab = Agt + ij*64;
                #pragma unroll
                for (int g = 0; g < 8; g++) {
                    ulonglong2 a0 = *(const ulonglong2*)(ab + g*8);
                    ulonglong2 a1 = *(const ulonglong2*)(ab + g*8 + 4);
                    FMA2(og[g], a0.x, v0);
                    FMA2(og[g], a0.y, v1);
                    FMA2(og[g], a1.x, v2);
                    FMA2(og[g], a1.y, v3);
                }
            }
        }
        __syncthreads();   // Agt/E reads done before Rs overwrites Ks
        #pragma unroll
        for (int g = 0; g < 8; g++) {
            float lo, hi; up2(og[g], lo, hi);
            Rs[w*264 + g*33 + c] = lo + hi;
        }
    }
    __syncthreads();

    // final reduce over 8 warps + scrambled store: out[b, g*32+px, py, c]
    {
        int c = tx, g = ty;
        float s = 0.f;
        #pragma unroll
        for (int w = 0; w < 8; w++) s += Rs[w*264 + g*33 + c];
        out[b*262144 + (g*32 + px)*1024 + py*32 + c] = s;
    }
}

// ---------------- launch ----------------
extern "C" void kernel_launch(void* const* d_in, const int* in_sizes, int n_in,
                              void* d_out, int out_size) {
    const float* x   = (const float*)d_in[0];
    const float* wq  = (const float*)d_in[1];
    const float* bq  = (const float*)d_in[2];
    const float* wk  = (const float*)d_in[3];
    const float* bk  = (const float*)d_in[4];
    const float* wv  = (const float*)d_in[5];
    const float* bv  = (const float*)d_in[6];
    const float* rlh = (const float*)d_in[7];
    const float* rlw = (const float*)d_in[8];
    float* out = (float*)d_out;

    cudaFuncSetAttribute(conv_kernel, cudaFuncAttributeMaxDynamicSharedMemorySize, CONV_SMEM);
    cudaFuncSetAttribute(attn_kernel, cudaFuncAttributeMaxDynamicSharedMemorySize, ATTN_SMEM);

    conv_kernel<<<dim3(28, 8, 4), 256, CONV_SMEM>>>(x, wq, bq, wk, bk, wv, bv);

    float* gv_ptr = nullptr;
    cudaGetSymbolAddress((void**)&gv_ptr, g_v);
    attn_kernel<<<NB*NPIX, 256, ATTN_SMEM>>>(rlh, rlw, gv_ptr, out);
}